// round 1
// baseline (speedup 1.0000x reference)
#include <cuda_runtime.h>
#include <math.h>
#include <stdint.h>

// ---------------- problem constants ----------------
#define BATCH   32768
#define KCODES  4096
#define DLAT    64
#define HIDDEN  1024
#define NHEAD   44      // 40 points + 2 widths + 2 alphas

// output layout (f32, reference return order, flattened+concat)
#define P_OFF    0
#define P_SIZE   (BATCH*40)
#define CP_OFF   (P_OFF + P_SIZE)
#define CP_SIZE  (BATCH*48)
#define W_OFF    (CP_OFF + CP_SIZE)
#define WA_SIZE  (BATCH*2)
#define A_OFF    (W_OFF + WA_SIZE)
#define LOSS_OFF (A_OFF + WA_SIZE)
#define IDX_OFF  (LOSS_OFF + 1)
#define PERP_OFF (IDX_OFF + BATCH)

// ---------------- scratch (__device__ globals; no allocation allowed) ----------------
__device__ float g_h1[BATCH*256];
__device__ float g_h2[BATCH*256];
__device__ float g_z [BATCH*DLAT];
__device__ float g_zq[BATCH*DLAT];
__device__ float g_d1[BATCH*HIDDEN];
__device__ float g_d2[BATCH*HIDDEN];
__device__ float g_ho[BATCH*NHEAD];
__device__ int   g_idx[BATCH];
__device__ float g_counts[KCODES];
__device__ float g_loss;
__device__ float g_enorm[KCODES];
__device__ float g_hw[HIDDEN*NHEAD];
__device__ float g_hb[NHEAD];

// ---------------- activations ----------------
#define ACT_NONE 0
#define ACT_LEAKY 1
#define ACT_SELU 2
#define ACT_HEAD 3

__device__ __forceinline__ float sigmoidf_(float x){ return 1.0f/(1.0f+expf(-x)); }

template<int ACT>
__device__ __forceinline__ float apply_act(float v, int col){
    if (ACT == ACT_LEAKY) return v > 0.0f ? v : 0.2f*v;
    if (ACT == ACT_SELU){
        const float a = 1.6732632423543772f, s = 1.0507009873554805f;
        return v > 0.0f ? s*v : s*a*(expf(v)-1.0f);
    }
    if (ACT == ACT_HEAD){
        if (col < 40) return tanhf(v)*12.0f + 14.0f;
        if (col < 42) return sigmoidf_(v)*2.0f + 1.0f;
        return sigmoidf_(v);
    }
    return v;
}

// ---------------- big SGEMM: C = act(A[M,K] @ W[K,N] + bias), 128x128x8, 8x8 microtile ----------------
template<int ACT>
__global__ void __launch_bounds__(256) sgemm128(
    const float* __restrict__ A, const float* __restrict__ W,
    const float* __restrict__ bias, float* __restrict__ C,
    int M, int N, int K)
{
    __shared__ float As[8][128];
    __shared__ float Bs[8][128];
    const int tid = threadIdx.x;
    const int bm = blockIdx.y * 128, bn = blockIdx.x * 128;
    const int arow = tid >> 1,  acol = (tid & 1) * 4;
    const int brow = tid >> 5,  bcol = (tid & 31) * 4;
    const int ty = tid >> 4, tx = tid & 15;

    float acc[8][8];
    #pragma unroll
    for (int i = 0; i < 8; i++)
        #pragma unroll
        for (int j = 0; j < 8; j++) acc[i][j] = 0.0f;

    const float* Aptr = A + (size_t)(bm + arow) * K + acol;
    const float* Wptr = W + (size_t)brow * N + bn + bcol;

    for (int k0 = 0; k0 < K; k0 += 8){
        float4 av = *(const float4*)(Aptr + k0);
        float4 bv = *(const float4*)(Wptr + (size_t)k0 * N);
        As[acol+0][arow] = av.x;
        As[acol+1][arow] = av.y;
        As[acol+2][arow] = av.z;
        As[acol+3][arow] = av.w;
        *(float4*)&Bs[brow][bcol] = bv;
        __syncthreads();
        #pragma unroll
        for (int kk = 0; kk < 8; kk++){
            float a[8], b[8];
            *(float4*)(a)   = *(const float4*)&As[kk][ty*8];
            *(float4*)(a+4) = *(const float4*)&As[kk][ty*8+4];
            *(float4*)(b)   = *(const float4*)&Bs[kk][tx*8];
            *(float4*)(b+4) = *(const float4*)&Bs[kk][tx*8+4];
            #pragma unroll
            for (int i = 0; i < 8; i++)
                #pragma unroll
                for (int j = 0; j < 8; j++)
                    acc[i][j] = fmaf(a[i], b[j], acc[i][j]);
        }
        __syncthreads();
    }

    float bsv[8];
    #pragma unroll
    for (int j = 0; j < 8; j++) bsv[j] = bias[bn + tx*8 + j];

    #pragma unroll
    for (int i = 0; i < 8; i++){
        float* cp = C + (size_t)(bm + ty*8 + i) * N + bn + tx*8;
        float4 v0, v1;
        v0.x = apply_act<ACT>(acc[i][0] + bsv[0], bn+tx*8+0);
        v0.y = apply_act<ACT>(acc[i][1] + bsv[1], bn+tx*8+1);
        v0.z = apply_act<ACT>(acc[i][2] + bsv[2], bn+tx*8+2);
        v0.w = apply_act<ACT>(acc[i][3] + bsv[3], bn+tx*8+3);
        v1.x = apply_act<ACT>(acc[i][4] + bsv[4], bn+tx*8+4);
        v1.y = apply_act<ACT>(acc[i][5] + bsv[5], bn+tx*8+5);
        v1.z = apply_act<ACT>(acc[i][6] + bsv[6], bn+tx*8+6);
        v1.w = apply_act<ACT>(acc[i][7] + bsv[7], bn+tx*8+7);
        *(float4*)(cp)   = v0;
        *(float4*)(cp+4) = v1;
    }
}

// ---------------- small-N SGEMM: 64 rows x N(<=64) cols, BK=16, 4x4 microtile ----------------
template<int ACT>
__global__ void __launch_bounds__(256) sgemm_smallN(
    const float* __restrict__ A, const float* __restrict__ W,
    const float* __restrict__ bias, float* __restrict__ C,
    int M, int N, int K)
{
    __shared__ float As[16][64];
    __shared__ float Bs[16][64];
    const int tid = threadIdx.x;
    const int bm = blockIdx.x * 64;
    const int arow = tid >> 2,  acol = (tid & 3) * 4;
    const int bkr  = tid >> 4,  bcol = (tid & 15) * 4;
    const int ty = tid >> 4, tx = tid & 15;

    float acc[4][4];
    #pragma unroll
    for (int i = 0; i < 4; i++)
        #pragma unroll
        for (int j = 0; j < 4; j++) acc[i][j] = 0.0f;

    for (int k0 = 0; k0 < K; k0 += 16){
        float4 av = *(const float4*)(A + (size_t)(bm + arow) * K + k0 + acol);
        As[acol+0][arow] = av.x;
        As[acol+1][arow] = av.y;
        As[acol+2][arow] = av.z;
        As[acol+3][arow] = av.w;
        float4 bv = make_float4(0.f,0.f,0.f,0.f);
        if (bcol < N) bv = *(const float4*)(W + (size_t)(k0 + bkr) * N + bcol);
        *(float4*)&Bs[bkr][bcol] = bv;
        __syncthreads();
        #pragma unroll
        for (int kk = 0; kk < 16; kk++){
            float a[4], b[4];
            *(float4*)a = *(const float4*)&As[kk][ty*4];
            *(float4*)b = *(const float4*)&Bs[kk][tx*4];
            #pragma unroll
            for (int i = 0; i < 4; i++)
                #pragma unroll
                for (int j = 0; j < 4; j++)
                    acc[i][j] = fmaf(a[i], b[j], acc[i][j]);
        }
        __syncthreads();
    }

    if (tx*4 < N){
        float bsv[4];
        #pragma unroll
        for (int j = 0; j < 4; j++) bsv[j] = bias[tx*4 + j];
        #pragma unroll
        for (int i = 0; i < 4; i++){
            float4 v;
            v.x = apply_act<ACT>(acc[i][0] + bsv[0], tx*4+0);
            v.y = apply_act<ACT>(acc[i][1] + bsv[1], tx*4+1);
            v.z = apply_act<ACT>(acc[i][2] + bsv[2], tx*4+2);
            v.w = apply_act<ACT>(acc[i][3] + bsv[3], tx*4+3);
            *(float4*)(C + (size_t)(bm + ty*4 + i) * N + tx*4) = v;
        }
    }
}

// ---------------- codebook norms ----------------
__global__ void enorm_kernel(const float* __restrict__ emb, float* __restrict__ enorm){
    int k = blockIdx.x * 256 + threadIdx.x;
    if (k >= KCODES) return;
    const float4* e = (const float4*)(emb + (size_t)k * DLAT);
    float s = 0.0f;
    #pragma unroll
    for (int q = 0; q < 16; q++){
        float4 v = e[q];
        s += v.x*v.x + v.y*v.y + v.z*v.z + v.w*v.w;
    }
    enorm[k] = s;
}

// ---------------- VQ argmin: 128 rows x 4096 codes, GEMM-style with fused argmin ----------------
__global__ void __launch_bounds__(256) vq_argmin(
    const float* __restrict__ z, const float* __restrict__ emb,
    const float* __restrict__ enorm, int* __restrict__ idx_out)
{
    extern __shared__ float sm[];
    float* Zs = sm;                 // [64][128]
    float* Es = sm + 64*128;        // [64][128]
    float* en = sm + 2*64*128;      // [128]
    const int tid = threadIdx.x;
    const int bm = blockIdx.x * 128;
    const int ty = tid >> 4, tx = tid & 15;
    const int lrow = tid >> 1, lhalf = (tid & 1) * 32;

    // load z tile transposed: Zs[d][row]
    #pragma unroll
    for (int q = 0; q < 8; q++){
        float4 v = *(const float4*)(z + (size_t)(bm + lrow) * DLAT + lhalf + q*4);
        Zs[(lhalf + q*4 + 0)*128 + lrow] = v.x;
        Zs[(lhalf + q*4 + 1)*128 + lrow] = v.y;
        Zs[(lhalf + q*4 + 2)*128 + lrow] = v.z;
        Zs[(lhalf + q*4 + 3)*128 + lrow] = v.w;
    }

    float mv[8]; int mi[8];
    #pragma unroll
    for (int i = 0; i < 8; i++){ mv[i] = INFINITY; mi[i] = 0; }

    for (int c0 = 0; c0 < KCODES; c0 += 128){
        __syncthreads();
        #pragma unroll
        for (int q = 0; q < 8; q++){
            float4 v = *(const float4*)(emb + (size_t)(c0 + lrow) * DLAT + lhalf + q*4);
            Es[(lhalf + q*4 + 0)*128 + lrow] = v.x;
            Es[(lhalf + q*4 + 1)*128 + lrow] = v.y;
            Es[(lhalf + q*4 + 2)*128 + lrow] = v.z;
            Es[(lhalf + q*4 + 3)*128 + lrow] = v.w;
        }
        if (tid < 128) en[tid] = enorm[c0 + tid];
        __syncthreads();

        float acc[8][8];
        #pragma unroll
        for (int i = 0; i < 8; i++)
            #pragma unroll
            for (int j = 0; j < 8; j++) acc[i][j] = 0.0f;

        #pragma unroll 4
        for (int d = 0; d < 64; d++){
            float a[8], b[8];
            *(float4*)(a)   = *(const float4*)&Zs[d*128 + ty*8];
            *(float4*)(a+4) = *(const float4*)&Zs[d*128 + ty*8 + 4];
            *(float4*)(b)   = *(const float4*)&Es[d*128 + tx*8];
            *(float4*)(b+4) = *(const float4*)&Es[d*128 + tx*8 + 4];
            #pragma unroll
            for (int i = 0; i < 8; i++)
                #pragma unroll
                for (int j = 0; j < 8; j++)
                    acc[i][j] = fmaf(a[i], b[j], acc[i][j]);
        }

        #pragma unroll
        for (int i = 0; i < 8; i++)
            #pragma unroll
            for (int j = 0; j < 8; j++){
                float s = en[tx*8 + j] - 2.0f * acc[i][j];
                int c = c0 + tx*8 + j;                    // ascending within thread
                if (s < mv[i]) { mv[i] = s; mi[i] = c; }  // strict < keeps first min
            }
    }

    __syncthreads();
    float* rv = Es;                        // reuse Es region
    int*   ri = (int*)(Es + 2048);
    #pragma unroll
    for (int i = 0; i < 8; i++){
        rv[tx*128 + ty*8 + i] = mv[i];
        ri[tx*128 + ty*8 + i] = mi[i];
    }
    __syncthreads();
    if (tid < 128){
        float bv = INFINITY; int bi = 0x7fffffff;
        #pragma unroll
        for (int t = 0; t < 16; t++){
            float v = rv[t*128 + tid];
            int c = ri[t*128 + tid];
            if (v < bv || (v == bv && c < bi)){ bv = v; bi = c; }
        }
        idx_out[bm + tid] = bi;
    }
}

// ---------------- gather z_q, idx-as-float, counts, commit-loss partial sums ----------------
__global__ void vq_post(const float* __restrict__ z, const float* __restrict__ emb,
                        const int* __restrict__ idx, float* __restrict__ zq,
                        float* __restrict__ counts, float* __restrict__ loss,
                        float* __restrict__ out_idx)
{
    int b = blockIdx.x * 256 + threadIdx.x;
    int k = idx[b];
    const float4* e  = (const float4*)(emb + (size_t)k * DLAT);
    const float4* zz = (const float4*)(z   + (size_t)b * DLAT);
    float4*       zo = (float4*)(zq + (size_t)b * DLAT);
    float s = 0.0f;
    #pragma unroll
    for (int q = 0; q < 16; q++){
        float4 ev = e[q], zv = zz[q];
        float dx = ev.x - zv.x, dy = ev.y - zv.y, dz = ev.z - zv.z, dw = ev.w - zv.w;
        s += dx*dx + dy*dy + dz*dz + dw*dw;
        zo[q] = ev;
    }
    out_idx[b] = (float)k;
    atomicAdd(&counts[k], 1.0f);

    __shared__ float red[256];
    red[threadIdx.x] = s;
    __syncthreads();
    for (int off = 128; off > 0; off >>= 1){
        if (threadIdx.x < off) red[threadIdx.x] += red[threadIdx.x + off];
        __syncthreads();
    }
    if (threadIdx.x == 0) atomicAdd(loss, red[0]);
}

// ---------------- perplexity + vq_loss scalars ----------------
__global__ void finalize_kernel(const float* __restrict__ counts, const float* __restrict__ loss,
                                float* __restrict__ out)
{
    __shared__ float red[256];
    float s = 0.0f;
    for (int k = threadIdx.x; k < KCODES; k += 256){
        float p = counts[k] * (1.0f / (float)BATCH);
        s += p * logf(p + 1e-10f);
    }
    red[threadIdx.x] = s;
    __syncthreads();
    for (int off = 128; off > 0; off >>= 1){
        if (threadIdx.x < off) red[threadIdx.x] += red[threadIdx.x + off];
        __syncthreads();
    }
    if (threadIdx.x == 0){
        out[PERP_OFF] = expf(-red[0]);
        out[LOSS_OFF] = loss[0] * (0.25f / ((float)BATCH * (float)DLAT));
    }
}

// ---------------- zero counts + loss ----------------
__global__ void zero_kernel(float* __restrict__ counts, float* __restrict__ loss){
    int i = blockIdx.x * 256 + threadIdx.x;
    if (i < KCODES) counts[i] = 0.0f;
    if (i == KCODES) loss[0] = 0.0f;
}

// ---------------- concat head weights [pW|wW|aW] -> [1024,44], biases -> [44] ----------------
__global__ void concat_head(const float* __restrict__ pW, const float* __restrict__ pb,
                            const float* __restrict__ wW, const float* __restrict__ wb,
                            const float* __restrict__ aW, const float* __restrict__ ab,
                            float* __restrict__ hw, float* __restrict__ hb)
{
    int i = blockIdx.x * 256 + threadIdx.x;
    int total = HIDDEN * NHEAD;
    if (i < total){
        int k = i / NHEAD, col = i % NHEAD;
        float v;
        if (col < 40)      v = pW[k*40 + col];
        else if (col < 42) v = wW[k*2 + (col-40)];
        else               v = aW[k*2 + (col-42)];
        hw[i] = v;
    }
    if (i < NHEAD){
        float v;
        if (i < 40)      v = pb[i];
        else if (i < 42) v = wb[i-40];
        else             v = ab[i-42];
        hb[i] = v;
    }
}

// ---------------- pack outputs: points / control_points / widths / alphas ----------------
__global__ void pack_kernel(const float* __restrict__ ho, float* __restrict__ out){
    int gid = blockIdx.x * 256 + threadIdx.x;
    int b = gid / 92, e = gid % 92;
    if (b >= BATCH) return;
    const float* h = ho + (size_t)b * NHEAD;
    if (e < 40){
        out[P_OFF + (size_t)b*40 + e] = h[e];
    } else if (e < 88){
        int e2 = e - 40;
        int c  = e2 & 1;
        int j  = (e2 >> 1) & 3;
        int sg = (e2 >> 3) % 3;
        int p  = e2 / 24;
        out[CP_OFF + (size_t)b*48 + e2] = h[p*20 + (3*sg + j)*2 + c];
    } else if (e < 90){
        int p = e - 88;
        out[W_OFF + (size_t)b*2 + p] = h[40 + p];
    } else {
        int p = e - 90;
        out[A_OFF + (size_t)b*2 + p] = h[42 + p];
    }
}

// ---------------- launch ----------------
extern "C" void kernel_launch(void* const* d_in, const int* in_sizes, int n_in,
                              void* d_out, int out_size)
{
    (void)in_sizes; (void)n_in; (void)out_size;
    const float* x   = (const float*)d_in[0];
    const float* W1  = (const float*)d_in[1];
    const float* b1  = (const float*)d_in[2];
    const float* W2  = (const float*)d_in[3];
    const float* b2  = (const float*)d_in[4];
    const float* W3  = (const float*)d_in[5];
    const float* b3  = (const float*)d_in[6];
    const float* emb = (const float*)d_in[7];
    const float* dW1 = (const float*)d_in[8];
    const float* db1 = (const float*)d_in[9];
    const float* dW2 = (const float*)d_in[10];
    const float* db2 = (const float*)d_in[11];
    const float* pW  = (const float*)d_in[12];
    const float* pb  = (const float*)d_in[13];
    const float* wW  = (const float*)d_in[14];
    const float* wb  = (const float*)d_in[15];
    const float* aW  = (const float*)d_in[16];
    const float* ab  = (const float*)d_in[17];
    float* out = (float*)d_out;

    float *h1, *h2, *z, *zq, *d1, *d2, *ho, *counts, *loss, *enorm, *hw, *hb;
    int* idx;
    cudaGetSymbolAddress((void**)&h1, g_h1);
    cudaGetSymbolAddress((void**)&h2, g_h2);
    cudaGetSymbolAddress((void**)&z,  g_z);
    cudaGetSymbolAddress((void**)&zq, g_zq);
    cudaGetSymbolAddress((void**)&d1, g_d1);
    cudaGetSymbolAddress((void**)&d2, g_d2);
    cudaGetSymbolAddress((void**)&ho, g_ho);
    cudaGetSymbolAddress((void**)&idx, g_idx);
    cudaGetSymbolAddress((void**)&counts, g_counts);
    cudaGetSymbolAddress((void**)&loss, g_loss);
    cudaGetSymbolAddress((void**)&enorm, g_enorm);
    cudaGetSymbolAddress((void**)&hw, g_hw);
    cudaGetSymbolAddress((void**)&hb, g_hb);

    cudaFuncSetAttribute(vq_argmin, cudaFuncAttributeMaxDynamicSharedMemorySize, 66048);

    // init scalars/counts + head-weight concat + codebook norms
    zero_kernel<<<(KCODES + 1 + 255)/256, 256>>>(counts, loss);
    concat_head<<<(HIDDEN*NHEAD + 255)/256, 256>>>(pW, pb, wW, wb, aW, ab, hw, hb);
    enorm_kernel<<<(KCODES + 255)/256, 256>>>(emb, enorm);

    // encoder
    sgemm128<ACT_LEAKY><<<dim3(256/128, BATCH/128), 256>>>(x,  W1, b1, h1, BATCH, 256, 784);
    sgemm128<ACT_LEAKY><<<dim3(256/128, BATCH/128), 256>>>(h1, W2, b2, h2, BATCH, 256, 256);
    sgemm_smallN<ACT_NONE><<<BATCH/64, 256>>>(h2, W3, b3, z, BATCH, DLAT, 256);

    // VQ
    vq_argmin<<<BATCH/128, 256, 66048>>>(z, emb, enorm, idx);
    vq_post<<<BATCH/256, 256>>>(z, emb, idx, zq, counts, loss, out + IDX_OFF);
    finalize_kernel<<<1, 256>>>(counts, loss, out);

    // decoder
    sgemm128<ACT_SELU><<<dim3(HIDDEN/128, BATCH/128), 256>>>(zq, dW1, db1, d1, BATCH, HIDDEN, DLAT);
    sgemm128<ACT_SELU><<<dim3(HIDDEN/128, BATCH/128), 256>>>(d1, dW2, db2, d2, BATCH, HIDDEN, HIDDEN);
    sgemm_smallN<ACT_HEAD><<<BATCH/64, 256>>>(d2, hw, hb, ho, BATCH, NHEAD, HIDDEN);

    // pack outputs
    pack_kernel<<<(BATCH*92 + 255)/256, 256>>>(ho, out);
}